// round 4
// baseline (speedup 1.0000x reference)
#include <cuda_runtime.h>

// Problem constants (fixed by the reference): B=2, C=DIMS=64, H=16, W=64,
// HEADS=64 -> per-head channels = 1, S = H*W = 1024.
#define SLEN 1024
#define CH   64
#define NB   2
#define NTOK (NB * CH * SLEN)   // 131072, layout index = (b*64+c)*1024 + s

#define MNODES 32               // Chebyshev nodes / coefficients per head

// log2(e) / sqrt(DIMS) = 1.4426950408889634 / 8
#define K_PRESCALE 0.18033688011112043f

// Scratch (allocation-free rule: __device__ globals)
__device__ float  g_q[NTOK];
__device__ float2 g_kv[NTOK];   // (k * K_PRESCALE, v) interleaved per token
__device__ float  g_o[NTOK];

__device__ __forceinline__ float ex2f(float x) {
    float r;
    asm("ex2.approx.f32 %0, %1;" : "=f"(r) : "f"(x));
    return r;
}

// ---------------------------------------------------------------------------
// Kernel A: QKV projections (1x1 conv == 64x64 channel-mix GEMM).
// One thread per (b, oc, s) output token; warp spans contiguous s -> coalesced
// x loads, CTA-uniform W loads (L1-resident).
// ---------------------------------------------------------------------------
__global__ void qkv_kernel(const float* __restrict__ x,
                           const float* __restrict__ Wq, const float* __restrict__ bq,
                           const float* __restrict__ Wk, const float* __restrict__ bk,
                           const float* __restrict__ Wv, const float* __restrict__ bv) {
    int tid = blockIdx.x * blockDim.x + threadIdx.x;   // == (b*64+oc)*1024 + s
    int s  = tid & (SLEN - 1);
    int oc = (tid >> 10) & (CH - 1);
    int b  = tid >> 16;

    const float* xb = x + b * (CH * SLEN) + s;   // x[b, c, s], stride SLEN over c
    float aq = __ldg(bq + oc);
    float ak = __ldg(bk + oc);
    float av = __ldg(bv + oc);

    #pragma unroll 8
    for (int c = 0; c < CH; c++) {
        float xv = __ldg(xb + c * SLEN);
        aq = fmaf(__ldg(Wq + oc * CH + c), xv, aq);
        ak = fmaf(__ldg(Wk + oc * CH + c), xv, ak);
        av = fmaf(__ldg(Wv + oc * CH + c), xv, av);
    }
    g_q[tid]  = aq;
    g_kv[tid] = make_float2(ak * K_PRESCALE, av);
}

// ---------------------------------------------------------------------------
// Kernel B (primary): Chebyshev-interpolated rank-1 attention.
// Per head: o(a) = N(a)/D(a), N(a)=sum_t v_t 2^{a k'_t}, D(a)=sum_t 2^{a k'_t},
// queried at a = q_s. Build a 32-node Chebyshev interpolant of N and D on
// [min q, max q] (32x fewer exps than direct eval), then Clenshaw per query.
// beta = half*|k'|*ln2 ~ 2 -> degree-31 interp error ~1e-30, below fp32 noise.
// One CTA of 1024 threads per head; lane = node, warp = 32-token t-chunk.
// ---------------------------------------------------------------------------
__global__ void __launch_bounds__(1024, 1) attn_cheb_kernel() {
    __shared__ float sk[SLEN];            // k' (prescaled)
    __shared__ float sv[SLEN];            // v
    __shared__ float pN[32 * 33];         // per-warp node partials (padded)
    __shared__ float pD[32 * 33];
    __shared__ float wlo[32], whi[32];    // per-warp q min/max
    __shared__ float nodeN[MNODES], nodeD[MNODES];
    __shared__ float cN[MNODES], cD[MNODES];
    __shared__ float s_mid, s_half;

    const int head = blockIdx.x;
    const int tid  = threadIdx.x;
    const int w    = tid >> 5;
    const int lane = tid & 31;

    // --- Stage k', v; fetch own query scalar ---
    float2 kv = g_kv[head * SLEN + tid];
    sk[tid] = kv.x;
    sv[tid] = kv.y;
    const float myq = g_q[head * SLEN + tid];

    // --- Block min/max of q (defines the interpolation interval) ---
    float lo = myq, hi = myq;
    #pragma unroll
    for (int off = 16; off > 0; off >>= 1) {
        lo = fminf(lo, __shfl_down_sync(0xffffffffu, lo, off));
        hi = fmaxf(hi, __shfl_down_sync(0xffffffffu, hi, off));
    }
    if (lane == 0) { wlo[w] = lo; whi[w] = hi; }
    __syncthreads();
    if (w == 0) {
        lo = wlo[lane]; hi = whi[lane];
        #pragma unroll
        for (int off = 16; off > 0; off >>= 1) {
            lo = fminf(lo, __shfl_down_sync(0xffffffffu, lo, off));
            hi = fmaxf(hi, __shfl_down_sync(0xffffffffu, hi, off));
        }
        if (lane == 0) {
            s_mid  = 0.5f * (lo + hi);
            s_half = fmaxf(0.5f * (hi - lo), 1e-20f);  // degenerate-range guard
        }
    }
    __syncthreads();
    const float mid = s_mid, half = s_half;

    // --- Node sums: lane = node j, warp = t-chunk [w*32, w*32+32) ---
    // a_j = mid + half * cos(pi (j+0.5)/32)
    const float aj = fmaf(half, cospif((lane + 0.5f) * (1.0f / 32.0f)), mid);
    float n = 0.f, d = 0.f;
    const int t0 = w * 32;
    #pragma unroll 8
    for (int i = 0; i < 32; i++) {
        float kk = sk[t0 + i];            // warp-uniform -> LDS broadcast
        float vv = sv[t0 + i];
        float e = ex2f(aj * kk);
        d += e;
        n = fmaf(e, vv, n);
    }
    pN[w * 33 + lane] = n;
    pD[w * 33 + lane] = d;
    __syncthreads();

    // --- Cross-warp reduce: warp j sums the 32 partials of node j ---
    {
        float nn = pN[lane * 33 + w];     // padded stride -> conflict-free
        float dd = pD[lane * 33 + w];
        #pragma unroll
        for (int off = 16; off > 0; off >>= 1) {
            nn += __shfl_down_sync(0xffffffffu, nn, off);
            dd += __shfl_down_sync(0xffffffffu, dd, off);
        }
        if (lane == 0) { nodeN[w] = nn; nodeD[w] = dd; }
    }
    __syncthreads();

    // --- DCT-II: c_i = (2/m) sum_j f_j cos(pi i (j+0.5)/m); warp0->N, warp1->D ---
    if (w < 2) {
        const float* f = (w == 0) ? nodeN : nodeD;
        float c = 0.f;
        for (int j = 0; j < MNODES; j++)
            c = fmaf(f[j], cospif((float)lane * (j + 0.5f) * (1.0f / 32.0f)), c);
        c *= (2.0f / MNODES);
        if (w == 0) cN[lane] = c; else cD[lane] = c;
    }
    __syncthreads();

    // --- Clenshaw evaluation at x = (q_s - mid)/half for N and D jointly ---
    // p(x) = c0/2 + sum_{i>=1} c_i T_i(x);  result = x*b1 - b2 + c0/2
    const float xq = (myq - mid) / half;
    const float x2 = 2.0f * xq;
    float bn1 = 0.f, bn2 = 0.f, bd1 = 0.f, bd2 = 0.f;
    for (int i = MNODES - 1; i >= 1; i--) {
        float tn = fmaf(x2, bn1, cN[i] - bn2);
        float td = fmaf(x2, bd1, cD[i] - bd2);
        bn2 = bn1; bn1 = tn;
        bd2 = bd1; bd1 = td;
    }
    const float Nv = fmaf(xq, bn1, 0.5f * cN[0] - bn2);
    const float Dv = fmaf(xq, bd1, 0.5f * cD[0] - bd2);

    g_o[head * SLEN + tid] = Nv / Dv;
}

// ---------------------------------------------------------------------------
// Kernel B (fallback, kept for one-line swap if Chebyshev misses rel_err):
// direct rank-1 attention, MUFU.EX2-bound (~32us standalone by model).
// ---------------------------------------------------------------------------
#define SCHUNK 128
#define NCHUNK (SLEN / SCHUNK)
__global__ void __launch_bounds__(SCHUNK) attn_direct_kernel() {
    __shared__ float2 skv[SLEN];
    const int head   = blockIdx.x >> 3;
    const int s_base = (blockIdx.x & (NCHUNK - 1)) * SCHUNK;
    const int tid    = threadIdx.x;

    const float4* gkv4 = reinterpret_cast<const float4*>(g_kv + head * SLEN);
    float4* skv4w = reinterpret_cast<float4*>(skv);
    #pragma unroll
    for (int i = 0; i < SLEN / 2 / SCHUNK; i++)
        skv4w[tid + i * SCHUNK] = gkv4[tid + i * SCHUNK];
    __syncthreads();

    const int s = s_base + tid;
    const float a = g_q[head * SLEN + s];
    const float4* skv4 = reinterpret_cast<const float4*>(skv);

    float n0 = 0.f, n1 = 0.f, d0 = 0.f, d1 = 0.f;
    #pragma unroll 8
    for (int t4 = 0; t4 < SLEN / 2; t4++) {
        float4 kk = skv4[t4];
        float e0 = ex2f(a * kk.x);
        float e1 = ex2f(a * kk.z);
        n0 = fmaf(e0, kk.y, n0);
        d0 += e0;
        n1 = fmaf(e1, kk.w, n1);
        d1 += e1;
    }
    g_o[head * SLEN + s] = (n0 + n1) / (d0 + d1);
}

// ---------------------------------------------------------------------------
// Kernel C: output projection + residual.
//   out[b,oc,s] = x[b,oc,s] + bo[oc] + sum_g Wo[oc,g] * o[b,g,s]
// ---------------------------------------------------------------------------
__global__ void out_kernel(const float* __restrict__ x,
                           const float* __restrict__ Wo, const float* __restrict__ bo,
                           float* __restrict__ out) {
    int tid = blockIdx.x * blockDim.x + threadIdx.x;
    int s  = tid & (SLEN - 1);
    int oc = (tid >> 10) & (CH - 1);
    int b  = tid >> 16;

    float acc = __ldg(bo + oc) + __ldg(x + tid);
    const float* ob = g_o + b * (CH * SLEN) + s;

    #pragma unroll 8
    for (int g = 0; g < CH; g++)
        acc = fmaf(__ldg(Wo + oc * CH + g), ob[g * SLEN], acc);

    out[tid] = acc;
}

// ---------------------------------------------------------------------------
extern "C" void kernel_launch(void* const* d_in, const int* in_sizes, int n_in,
                              void* d_out, int out_size) {
    const float* x  = (const float*)d_in[0];
    const float* Wq = (const float*)d_in[1];
    const float* bq = (const float*)d_in[2];
    const float* Wk = (const float*)d_in[3];
    const float* bk = (const float*)d_in[4];
    const float* Wv = (const float*)d_in[5];
    const float* bv = (const float*)d_in[6];
    const float* Wo = (const float*)d_in[7];
    const float* bo = (const float*)d_in[8];
    float* out = (float*)d_out;

    qkv_kernel<<<NTOK / 256, 256>>>(x, Wq, bq, Wk, bk, Wv, bv);
    attn_cheb_kernel<<<NB * CH, 1024>>>();
    // Fallback (swap if rel_err fails): attn_direct_kernel<<<NB*CH*NCHUNK, SCHUNK>>>();
    out_kernel<<<NTOK / 256, 256>>>(x, Wo, bo, out);
}